// round 15
// baseline (speedup 1.0000x reference)
#include <cuda_runtime.h>
#include <cuda_fp16.h>
#include <cstdint>
#include <math.h>

#define NN 100000
#define EE 1600000
#define RSH 72             // fp16 row stride (halves) - all MMA buffers/weights
#define RSM 136            // fp16 m/ex/delta buffer row stride (halves)
#define SCAN_T 512
#define SCAN_B ((NN + SCAN_T - 1) / SCAN_T)   // 196

// ---------------- device scratch ----------------
__device__ __half g_asrc[NN * 64];
__device__ __half g_adst[NN * 64];
__device__ __half g_v[NN * 64];
__device__ float  g_num[NN * 64];
__device__ float  g_den[NN * 64];
__device__ int    g_cnt[NN];
__device__ int    g_off[NN];
__device__ int    g_cur[NN];
__device__ int    g_bsum[SCAN_B];
__device__ int2   g_sedge[EE];    // packed (src, dst), dst-sorted

// ---------------- helpers ----------------
__device__ __forceinline__ void red_add4(float* p, float4 v) {
    asm volatile("red.global.add.v4.f32 [%0], {%1,%2,%3,%4};"
                 :: "l"(p), "f"(v.x), "f"(v.y), "f"(v.z), "f"(v.w) : "memory");
}
__device__ __forceinline__ void mma_f16(float c[4], unsigned a0, unsigned a1,
                                        unsigned a2, unsigned a3,
                                        unsigned b0, unsigned b1) {
    asm volatile(
        "mma.sync.aligned.m16n8k16.row.col.f32.f16.f16.f32 "
        "{%0,%1,%2,%3},{%4,%5,%6,%7},{%8,%9},{%0,%1,%2,%3};"
        : "+f"(c[0]), "+f"(c[1]), "+f"(c[2]), "+f"(c[3])
        : "r"(a0), "r"(a1), "r"(a2), "r"(a3), "r"(b0), "r"(b1));
}
__device__ __forceinline__ void ldsm4(unsigned addr, unsigned& r0, unsigned& r1,
                                      unsigned& r2, unsigned& r3) {
    asm volatile("ldmatrix.sync.aligned.m8n8.x4.shared.b16 {%0,%1,%2,%3}, [%4];"
                 : "=r"(r0), "=r"(r1), "=r"(r2), "=r"(r3) : "r"(addr));
}

// ---- fp16 ldsm GEMM: A rows [rbase, rbase+16) x 64 halves @RSH, W 64x64 @RSH ----
__device__ __forceinline__ void gemm_h16(const __half* __restrict__ bufH,
                                         const __half* __restrict__ WH,
                                         int rbase, int lane, float acc[8][4]) {
    unsigned aA = (unsigned)__cvta_generic_to_shared(bufH)
                + (unsigned)((rbase + (lane & 15)) * (RSH * 2) + ((lane >> 4) << 4));
    unsigned bA = (unsigned)__cvta_generic_to_shared(WH)
                + (unsigned)(((lane & 7) + ((lane & 16) >> 1)) * (RSH * 2)
                             + ((lane & 8) ? 16 : 0));
#pragma unroll
    for (int kb = 0; kb < 4; kb++) {
        unsigned a0, a1, a2, a3;
        ldsm4(aA + kb * 32, a0, a1, a2, a3);
#pragma unroll
        for (int p = 0; p < 4; p++) {
            unsigned b0, b1, b2, b3;
            ldsm4(bA + (unsigned)(p * 16 * RSH * 2 + kb * 32), b0, b1, b2, b3);
            mma_f16(acc[2 * p],     a0, a1, a2, a3, b0, b1);
            mma_f16(acc[2 * p + 1], a0, a1, a2, a3, b2, b3);
        }
    }
}

__device__ __forceinline__ void zero_acc8(float acc[8][4]) {
#pragma unroll
    for (int nt = 0; nt < 8; nt++)
#pragma unroll
        for (int j = 0; j < 4; j++) acc[nt][j] = 0.f;
}

// ---------------- sort chain ----------------
__global__ void hist_kernel(const int* __restrict__ dst) {
    int i = blockIdx.x * blockDim.x + threadIdx.x;
    int stride = gridDim.x * blockDim.x;
    for (; i < EE; i += stride) atomicAdd(&g_cnt[dst[i]], 1);
}

__global__ void scan1_kernel() {
    __shared__ int s[SCAN_T];
    int tid = threadIdx.x;
    int i = blockIdx.x * SCAN_T + tid;
    int v = (i < NN) ? g_cnt[i] : 0;
    s[tid] = v;
    __syncthreads();
#pragma unroll
    for (int off = 1; off < SCAN_T; off <<= 1) {
        int t2 = (tid >= off) ? s[tid - off] : 0;
        __syncthreads();
        s[tid] += t2;
        __syncthreads();
    }
    if (i < NN) g_off[i] = s[tid] - v;
    if (tid == SCAN_T - 1) g_bsum[blockIdx.x] = s[SCAN_T - 1];
}

__global__ void scan2_kernel() {
    __shared__ int s[SCAN_T];
    int tid = threadIdx.x;
    int v = (tid < SCAN_B) ? g_bsum[tid] : 0;
    s[tid] = v;
    __syncthreads();
#pragma unroll
    for (int off = 1; off < SCAN_T; off <<= 1) {
        int t2 = (tid >= off) ? s[tid - off] : 0;
        __syncthreads();
        s[tid] += t2;
        __syncthreads();
    }
    if (tid < SCAN_B) g_bsum[tid] = s[tid] - v;
}

__global__ void scan3_kernel() {
    int i = blockIdx.x * SCAN_T + threadIdx.x;
    if (i < NN) {
        int o = g_off[i] + g_bsum[blockIdx.x];
        g_off[i] = o;
        g_cur[i] = o;
    }
}

__global__ void scatter_kernel(const int* __restrict__ src,
                               const int* __restrict__ dst) {
    int i = blockIdx.x * blockDim.x + threadIdx.x;
    int stride = gridDim.x * blockDim.x;
    for (; i < EE; i += stride) {
        int d = dst[i];
        int p = atomicAdd(&g_cur[d], 1);
        g_sedge[p] = make_int2(src[i], d);
    }
}

// ============================================================================
// node_prep (256 thr, 128-node tiles) — fp16 MMA, fp16 outputs
// ============================================================================
__global__ void __launch_bounds__(256) node_prep(
    const float* __restrict__ x,
    const float* __restrict__ W_in, const float* __restrict__ b_in,
    const float* __restrict__ W_lin, const float* __restrict__ W_src,
    const float* __restrict__ W_dst)
{
    extern __shared__ float sm[];
    __half* WinH = (__half*)sm;            // 4608 halves each
    __half* WsH  = WinH + 4608;
    __half* WdH  = WinH + 9216;
    __half* WlH  = WinH + 13824;           // ends at 9216 floats
    float*  bin  = sm + 9216;              // 64
    __half* bufA = (__half*)(sm + 9280);   // 9216 halves
    __half* bufB = bufA + 9216;            // -> total 18496 floats

    int t = threadIdx.x;
    for (int i = t; i < 4096; i += 256) {
        int k = i >> 6, n = i & 63;
        WinH[n * RSH + k] = __float2half_rn(W_in[i]);
        WsH[n * RSH + k]  = __float2half_rn(W_src[i]);
        WdH[n * RSH + k]  = __float2half_rn(W_dst[i]);
        WlH[n * RSH + k]  = __float2half_rn(W_lin[i]);
    }
    if (t < 64) bin[t] = b_in[t];
    __syncthreads();

    int w = t >> 5, lane = t & 31;
    int rbase = w * 16;
    int er0 = rbase + (lane >> 2);
    int cfr = 2 * (lane & 3);
    int ntiles = (NN + 127) / 128;

    for (int tile = blockIdx.x; tile < ntiles; tile += gridDim.x) {
        int base = tile * 128;
        __syncthreads();
#pragma unroll
        for (int rr = 0; rr < 8; rr++) {
            int i = t + 256 * rr;
            int row = i >> 4, col = (i & 15) * 4;
            int n = base + row;
            float4 v = make_float4(0, 0, 0, 0);
            if (n < NN) v = *(const float4*)&x[(size_t)n * 64 + col];
            *(__half2*)&bufA[(size_t)row * RSH + col] = __floats2half2_rn(v.x, v.y);
            *(__half2*)&bufA[(size_t)row * RSH + col + 2] = __floats2half2_rn(v.z, v.w);
        }
        __syncthreads();

        {
            float acc[8][4];
            zero_acc8(acc);
            gemm_h16(bufA, WinH, rbase, lane, acc);
#pragma unroll
            for (int nt = 0; nt < 8; nt++) {
                int col = nt * 8 + cfr;
                float2 b = *(const float2*)&bin[col];
                *(__half2*)&bufB[(size_t)er0 * RSH + col] =
                    __floats2half2_rn(fmaxf(acc[nt][0] + b.x, 0.f),
                                      fmaxf(acc[nt][1] + b.y, 0.f));
                *(__half2*)&bufB[(size_t)(er0 + 8) * RSH + col] =
                    __floats2half2_rn(fmaxf(acc[nt][2] + b.x, 0.f),
                                      fmaxf(acc[nt][3] + b.y, 0.f));
            }
        }
        __syncthreads();

        const __half* WHs[3] = {WsH, WdH, WlH};
        __half* outs[3] = {g_asrc, g_adst, g_v};
        int n0r = base + er0;
#pragma unroll
        for (int p = 0; p < 3; p++) {
            float acc[8][4];
            zero_acc8(acc);
            gemm_h16(bufB, WHs[p], rbase, lane, acc);
#pragma unroll
            for (int nt = 0; nt < 8; nt++) {
                int col = nt * 8 + cfr;
                if (n0r < NN)
                    *(__half2*)&outs[p][(size_t)n0r * 64 + col] =
                        __floats2half2_rn(acc[nt][0], acc[nt][1]);
                if (n0r + 8 < NN)
                    *(__half2*)&outs[p][(size_t)(n0r + 8) * 64 + col] =
                        __floats2half2_rn(acc[nt][2], acc[nt][3]);
            }
        }
    }
}

// ============================================================================
// edge kernel: warp-autonomous 16-edge tiles, dst-sorted (int2), fp16 MMA,
// fp16 gathers, delta staged in smem (fp16), run-aggregated scatter.
// 384 thr (12 warps), 2 CTAs/SM -> 24 warps/SM.
// ============================================================================
__global__ void __launch_bounds__(384, 2) edge_kernel(
    const float* __restrict__ pos,
    const float* __restrict__ posw1, const float* __restrict__ posb1,
    const float* __restrict__ posw2, const float* __restrict__ posb2,
    const float* __restrict__ attw1, const float* __restrict__ attb1,
    const float* __restrict__ attw2, const float* __restrict__ attb2)
{
    extern __shared__ float sm[];
    float* sw1  = sm;              // 192
    float* sb1  = sm + 192;        // 64
    float* sb2  = sm + 256;        // 64
    float* sab1 = sm + 320;        // 64
    float* sab2 = sm + 384;        // 64 -> 448
    __half* WhBase = (__half*)(sm + 448);
    __half* wp2H = WhBase;
    __half* wa1H = WhBase + 4608;
    __half* wa2H = WhBase + 9216;  // ends at 7360 floats

    int t = threadIdx.x;
    int wid = t >> 5, lane = t & 31;
    float*  wbase = sm + 7360 + wid * 1696;
    __half* wbufM = (__half*)wbase;            // 16*RSM = 2176 halves
    __half* wbufH = (__half*)(wbase + 1088);   // 16*RSH = 1152 halves
    int*    sidx  = (int*)(wbase + 1664);      // 16
    int*    didx  = sidx + 16;                 // 16 -> total 7360+12*1696=27712 floats

    for (int i = t; i < 4096; i += 384) {
        int k = i >> 6, n = i & 63;
        wp2H[n * RSH + k] = __float2half_rn(posw2[i]);
        wa1H[n * RSH + k] = __float2half_rn(attw1[i]);
        wa2H[n * RSH + k] = __float2half_rn(attw2[i]);
    }
    if (t < 192) sw1[t] = posw1[t];
    if (t < 64) { sb1[t] = posb1[t]; sb2[t] = posb2[t];
                  sab1[t] = attb1[t]; sab2[t] = attb2[t]; }
    __syncthreads();

    int el  = lane >> 1;             // row-layout: local edge 0..15
    int c0r = (lane & 1) * 32;       // row-layout: 32 channels per lane
    int er0 = lane >> 2;             // frag rows er0, er0+8
    int cfr = 2 * (lane & 3);        // frag col offset
    int part = (lane < 16) ? 4 * lane : 64 + 4 * (lane - 16);  // reduce slot

    const int nwt = gridDim.x * 12;
    for (int wt = blockIdx.x * 12 + wid; wt < EE / 16; wt += nwt) {
        int ebase = wt * 16;
        __syncwarp();
        if (lane < 16) {
            int2 e = g_sedge[ebase + lane];
            sidx[lane] = e.x;
            didx[lane] = e.y;
        }
        __syncwarp();

        int sE = sidx[el], dE = didx[el];
        // ---- layer 1 (K=3, scalar): h1 -> wbufH (fp16) ----
        {
            float p0 = __ldg(pos + dE * 3 + 0) - __ldg(pos + sE * 3 + 0);
            float p1 = __ldg(pos + dE * 3 + 1) - __ldg(pos + sE * 3 + 1);
            float p2 = __ldg(pos + dE * 3 + 2) - __ldg(pos + sE * 3 + 2);
#pragma unroll
            for (int j = 0; j < 8; j++) {
                int col = c0r + 4 * j;
                float4 b   = *(float4*)&sb1[col];
                float4 w0  = *(float4*)&sw1[col];
                float4 w1r = *(float4*)&sw1[64 + col];
                float4 w2r = *(float4*)&sw1[128 + col];
                float ax = fmaxf(fmaf(p2, w2r.x, fmaf(p1, w1r.x, fmaf(p0, w0.x, b.x))), 0.f);
                float ay = fmaxf(fmaf(p2, w2r.y, fmaf(p1, w1r.y, fmaf(p0, w0.y, b.y))), 0.f);
                float az = fmaxf(fmaf(p2, w2r.z, fmaf(p1, w1r.z, fmaf(p0, w0.z, b.z))), 0.f);
                float aw = fmaxf(fmaf(p2, w2r.w, fmaf(p1, w1r.w, fmaf(p0, w0.w, b.w))), 0.f);
                *(__half2*)&wbufH[el * RSH + col]     = __floats2half2_rn(ax, ay);
                *(__half2*)&wbufH[el * RSH + col + 2] = __floats2half2_rn(az, aw);
            }
        }
        __syncwarp();

        // ---- layer 2 (fp16 MMA): delta -> wbufM[64..128) (fp16); t -> wbufH ----
        int d0 = didx[er0], d1 = didx[er0 + 8];
        int s0 = sidx[er0], s1 = sidx[er0 + 8];
        {
            float acc[8][4];
            zero_acc8(acc);
            gemm_h16(wbufH, wp2H, 0, lane, acc);
            __syncwarp();
#pragma unroll
            for (int nt = 0; nt < 8; nt++) {
                int col = nt * 8 + cfr;
                float2 ad0 = __half22float2(*(const __half2*)&g_adst[(size_t)d0 * 64 + col]);
                float2 ad1 = __half22float2(*(const __half2*)&g_adst[(size_t)d1 * 64 + col]);
                float2 as0 = __half22float2(*(const __half2*)&g_asrc[(size_t)s0 * 64 + col]);
                float2 as1 = __half22float2(*(const __half2*)&g_asrc[(size_t)s1 * 64 + col]);
                float2 b = *(const float2*)&sb2[col];
                float D00 = fmaxf(acc[nt][0] + b.x, 0.f);
                float D01 = fmaxf(acc[nt][1] + b.y, 0.f);
                float D10 = fmaxf(acc[nt][2] + b.x, 0.f);
                float D11 = fmaxf(acc[nt][3] + b.y, 0.f);
                // stage delta in wbufM (ex region, unused until layer 4)
                *(__half2*)&wbufM[er0 * RSM + 64 + col] = __floats2half2_rn(D00, D01);
                *(__half2*)&wbufM[(er0 + 8) * RSM + 64 + col] = __floats2half2_rn(D10, D11);
                *(__half2*)&wbufH[er0 * RSH + col] =
                    __floats2half2_rn(ad0.x - as0.x + D00, ad0.y - as0.y + D01);
                *(__half2*)&wbufH[(er0 + 8) * RSH + col] =
                    __floats2half2_rn(ad1.x - as1.x + D10, ad1.y - as1.y + D11);
            }
        }
        __syncwarp();

        // ---- layer 3 (fp16 MMA): h2 = relu(t@attW1+b1) -> wbufH ----
        {
            float acc[8][4];
            zero_acc8(acc);
            gemm_h16(wbufH, wa1H, 0, lane, acc);
            __syncwarp();
#pragma unroll
            for (int nt = 0; nt < 8; nt++) {
                int col = nt * 8 + cfr;
                float2 b = *(const float2*)&sab1[col];
                *(__half2*)&wbufH[er0 * RSH + col] =
                    __floats2half2_rn(fmaxf(acc[nt][0] + b.x, 0.f),
                                      fmaxf(acc[nt][1] + b.y, 0.f));
                *(__half2*)&wbufH[(er0 + 8) * RSH + col] =
                    __floats2half2_rn(fmaxf(acc[nt][2] + b.x, 0.f),
                                      fmaxf(acc[nt][3] + b.y, 0.f));
            }
        }
        __syncwarp();

        // ---- layer 4 (fp16 MMA) + m/ex store (fp16); delta read-then-overwrite ----
        {
            float acc[8][4];
            zero_acc8(acc);
            gemm_h16(wbufH, wa2H, 0, lane, acc);
            __syncwarp();
#pragma unroll
            for (int nt = 0; nt < 8; nt++) {
                int col = nt * 8 + cfr;
                float2 v0 = __half22float2(*(const __half2*)&g_v[(size_t)s0 * 64 + col]);
                float2 v1 = __half22float2(*(const __half2*)&g_v[(size_t)s1 * 64 + col]);
                float2 D0 = __half22float2(*(const __half2*)&wbufM[er0 * RSM + 64 + col]);
                float2 D1 = __half22float2(*(const __half2*)&wbufM[(er0 + 8) * RSM + 64 + col]);
                float2 b = *(const float2*)&sab2[col];
                float e00 = __expf(fmaxf(acc[nt][0] + b.x, 0.f));
                float e01 = __expf(fmaxf(acc[nt][1] + b.y, 0.f));
                float e10 = __expf(fmaxf(acc[nt][2] + b.x, 0.f));
                float e11 = __expf(fmaxf(acc[nt][3] + b.y, 0.f));
                // m -> cols [0,64)
                *(__half2*)&wbufM[er0 * RSM + col] =
                    __floats2half2_rn(e00 * (v0.x + D0.x), e01 * (v0.y + D0.y));
                *(__half2*)&wbufM[(er0 + 8) * RSM + col] =
                    __floats2half2_rn(e10 * (v1.x + D1.x), e11 * (v1.y + D1.y));
                // ex -> cols [64,128) (overwrites delta after the read above)
                *(__half2*)&wbufM[er0 * RSM + 64 + col] = __floats2half2_rn(e00, e01);
                *(__half2*)&wbufM[(er0 + 8) * RSM + 64 + col] = __floats2half2_rn(e10, e11);
            }
        }
        __syncwarp();

        // ---- run-aggregated scatter: one red.v4 warp-op per distinct dst ----
        {
            int i = 0;
            while (i < 16) {
                int d = didx[i];
                float4 a4 = make_float4(0.f, 0.f, 0.f, 0.f);
                int j = i;
                do {
                    const __half2* p = (const __half2*)&wbufM[j * RSM + part];
                    float2 lo = __half22float2(p[0]);
                    float2 hi = __half22float2(p[1]);
                    a4.x += lo.x; a4.y += lo.y; a4.z += hi.x; a4.w += hi.y;
                    j++;
                } while (j < 16 && didx[j] == d);
                float* tgt = (lane < 16)
                    ? &g_num[(size_t)d * 64 + 4 * lane]
                    : &g_den[(size_t)d * 64 + 4 * (lane - 16)];
                red_add4(tgt, a4);
                i = j;
            }
        }
    }
}

// ============================================================================
// final (256 thr): out = relu((num/den)@W_out + b_out) — fp16 MMA
// ============================================================================
__global__ void __launch_bounds__(256) final_kernel(
    const float* __restrict__ W_out, const float* __restrict__ b_out,
    float* __restrict__ out)
{
    extern __shared__ float sm[];
    __half* WoH  = (__half*)sm;            // 2304 floats
    float*  bo   = sm + 2304;              // 64
    __half* bufA = (__half*)(sm + 2368);   // 4608 floats -> 6976 floats

    int t = threadIdx.x;
    for (int i = t; i < 4096; i += 256) {
        int k = i >> 6, n = i & 63;
        WoH[n * RSH + k] = __float2half_rn(W_out[i]);
    }
    if (t < 64) bo[t] = b_out[t];
    __syncthreads();

    int w = t >> 5, lane = t & 31;
    int rbase = w * 16;
    int er0 = rbase + (lane >> 2);
    int cfr = 2 * (lane & 3);
    int ntiles = (NN + 127) / 128;

    for (int tile = blockIdx.x; tile < ntiles; tile += gridDim.x) {
        int base = tile * 128;
        __syncthreads();
#pragma unroll
        for (int rr = 0; rr < 8; rr++) {
            int i = t + 256 * rr;
            int row = i >> 4, col = (i & 15) * 4;
            int n = base + row;
            float4 v = make_float4(0, 0, 0, 0);
            if (n < NN) {
                float4 nu = *(const float4*)&g_num[(size_t)n * 64 + col];
                float4 de = *(const float4*)&g_den[(size_t)n * 64 + col];
                v.x = nu.x / (de.x + 1e-16f);
                v.y = nu.y / (de.y + 1e-16f);
                v.z = nu.z / (de.z + 1e-16f);
                v.w = nu.w / (de.w + 1e-16f);
            }
            *(__half2*)&bufA[(size_t)row * RSH + col] = __floats2half2_rn(v.x, v.y);
            *(__half2*)&bufA[(size_t)row * RSH + col + 2] = __floats2half2_rn(v.z, v.w);
        }
        __syncthreads();

        float acc[8][4];
        zero_acc8(acc);
        gemm_h16(bufA, WoH, rbase, lane, acc);

        int n0r = base + er0;
#pragma unroll
        for (int nt = 0; nt < 8; nt++) {
            int col = nt * 8 + cfr;
            float2 b = *(const float2*)&bo[col];
            if (n0r < NN)
                *(float2*)&out[(size_t)n0r * 64 + col] =
                    make_float2(fmaxf(acc[nt][0] + b.x, 0.f),
                                fmaxf(acc[nt][1] + b.y, 0.f));
            if (n0r + 8 < NN)
                *(float2*)&out[(size_t)(n0r + 8) * 64 + col] =
                    make_float2(fmaxf(acc[nt][2] + b.x, 0.f),
                                fmaxf(acc[nt][3] + b.y, 0.f));
        }
    }
}

// ---------------- launch ----------------
extern "C" void kernel_launch(void* const* d_in, const int* in_sizes, int n_in,
                              void* d_out, int out_size)
{
    const float* x      = (const float*)d_in[0];
    const float* pos    = (const float*)d_in[1];
    const int*   ei     = (const int*)d_in[2];
    const float* W_in   = (const float*)d_in[3];
    const float* b_in   = (const float*)d_in[4];
    const float* W_out  = (const float*)d_in[5];
    const float* b_out  = (const float*)d_in[6];
    const float* W_lin  = (const float*)d_in[7];
    const float* W_src  = (const float*)d_in[8];
    const float* W_dst  = (const float*)d_in[9];
    const float* posw1  = (const float*)d_in[10];
    const float* posb1  = (const float*)d_in[11];
    const float* posw2  = (const float*)d_in[12];
    const float* posb2  = (const float*)d_in[13];
    const float* attw1  = (const float*)d_in[14];
    const float* attb1  = (const float*)d_in[15];
    const float* attw2  = (const float*)d_in[16];
    const float* attb2  = (const float*)d_in[17];
    float* out = (float*)d_out;

    const int NP_SMEM = 18496 * 4;   // 72.25 KB
    const int EK_SMEM = 27712 * 4;   // 108.25 KB -> 2 CTAs (384 thr) / SM
    const int FN_SMEM = 6976 * 4;    // 27.25 KB
    cudaFuncSetAttribute(node_prep, cudaFuncAttributeMaxDynamicSharedMemorySize, NP_SMEM);
    cudaFuncSetAttribute(edge_kernel, cudaFuncAttributeMaxDynamicSharedMemorySize, EK_SMEM);
    cudaFuncSetAttribute(final_kernel, cudaFuncAttributeMaxDynamicSharedMemorySize, FN_SMEM);

    const int* srcp = ei;
    const int* dstp = ei + EE;

    // zero accumulators + histogram via memset nodes (graph-capturable)
    void* p_num; void* p_den; void* p_cnt;
    cudaGetSymbolAddress(&p_num, g_num);
    cudaGetSymbolAddress(&p_den, g_den);
    cudaGetSymbolAddress(&p_cnt, g_cnt);
    cudaMemsetAsync(p_num, 0, (size_t)NN * 64 * sizeof(float));
    cudaMemsetAsync(p_den, 0, (size_t)NN * 64 * sizeof(float));
    cudaMemsetAsync(p_cnt, 0, (size_t)NN * sizeof(int));

    hist_kernel<<<1024, 256>>>(dstp);
    scan1_kernel<<<SCAN_B, SCAN_T>>>();
    scan2_kernel<<<1, SCAN_T>>>();
    scan3_kernel<<<SCAN_B, SCAN_T>>>();
    scatter_kernel<<<1024, 256>>>(srcp, dstp);
    node_prep<<<296, 256, NP_SMEM>>>(x, W_in, b_in, W_lin, W_src, W_dst);
    edge_kernel<<<296, 384, EK_SMEM>>>(pos,
                                       posw1, posb1, posw2, posb2,
                                       attw1, attb1, attw2, attb2);
    final_kernel<<<444, 256, FN_SMEM>>>(W_out, b_out, out);
}